// round 1
// baseline (speedup 1.0000x reference)
#include <cuda_runtime.h>
#include <cstddef>

// LocalVariation: out[b,k,y,x] = x[b,y,x] - x[b, clamp(y+i-2), clamp(x+j-2)]
// for k enumerating the 24 off-center (i,j) positions of a 5x5 window.
// Shapes: x [16,1,512,512] f32 -> out [16,24,512,512] f32.
//
// Write-bound kernel (402 MB stores). One CTA per (batch,row): stage the 5
// clamped input rows in SMEM, each thread produces 4 contiguous pixels for
// all 24 channels via STG.128.

#define KSZ 5
#define P   2
#define NBR 24
#define H   512
#define W   512
#define BATCH 16

// padded shared row: 516 valid cols (x in [-2, 513]) -> stride 520 floats
// (multiple of 8 -> 16B-aligned rows, 8-bank shift per row)
#define SROW 520
#define SCOLS 516

__global__ __launch_bounds__(128, 8)
void LocalVariation_kernel(const float* __restrict__ x, float* __restrict__ out)
{
    __shared__ float s[KSZ * SROW];

    const int y = blockIdx.x;   // 0..511
    const int b = blockIdx.y;   // 0..15
    const int tid = threadIdx.x; // 0..127

    const float* __restrict__ xb = x + (size_t)b * H * W;

    // Stage 5 rows (y-2 .. y+2, clamped) with x replicate-pad into SMEM.
    // 5*516 = 2580 scalar loads across 128 threads (~20 each); input is
    // L2-resident so these are cheap.
    #pragma unroll 4
    for (int idx = tid; idx < KSZ * SCOLS; idx += 128) {
        const int r   = idx / SCOLS;
        const int col = idx - r * SCOLS;          // 0..515  (maps to x = col-2)
        int gy = y + r - P;
        gy = gy < 0 ? 0 : (gy > H - 1 ? H - 1 : gy);
        int gx = col - P;
        gx = gx < 0 ? 0 : (gx > W - 1 ? W - 1 : gx);
        s[r * SROW + col] = __ldg(&xb[gy * W + gx]);
    }
    __syncthreads();

    const int x0 = tid * 4;      // this thread's 4 output pixels: x0..x0+3

    // Pull an 8-wide register window per row: positions x0 .. x0+7
    // (neighbor index = x0 + j + dx, j in [0,4], dx in [0,3]).
    // s[r*SROW + x0] is 16B-aligned (SROW%8==0, x0%4==0) -> LDS.128, no conflicts.
    float r[KSZ][8];
    #pragma unroll
    for (int i = 0; i < KSZ; i++) {
        const float4 lo = *reinterpret_cast<const float4*>(&s[i * SROW + x0]);
        const float4 hi = *reinterpret_cast<const float4*>(&s[i * SROW + x0 + 4]);
        r[i][0] = lo.x; r[i][1] = lo.y; r[i][2] = lo.z; r[i][3] = lo.w;
        r[i][4] = hi.x; r[i][5] = hi.y; r[i][6] = hi.z; r[i][7] = hi.w;
    }

    // Center pixels x0+dx -> s[2][x0+dx+2] -> r[2][dx+2]
    const float c0 = r[P][2];
    const float c1 = r[P][3];
    const float c2 = r[P][4];
    const float c3 = r[P][5];

    float* __restrict__ ob = out + (((size_t)b * NBR) * H + y) * W + x0;

    int k = 0;
    #pragma unroll
    for (int i = 0; i < KSZ; i++) {
        #pragma unroll
        for (int j = 0; j < KSZ; j++) {
            if (i == P && j == P) continue;
            float4 v;
            v.x = c0 - r[i][j + 0];
            v.y = c1 - r[i][j + 1];
            v.z = c2 - r[i][j + 2];
            v.w = c3 - r[i][j + 3];
            *reinterpret_cast<float4*>(ob + (size_t)k * (H * W)) = v;
            k++;
        }
    }
}

extern "C" void kernel_launch(void* const* d_in, const int* in_sizes, int n_in,
                              void* d_out, int out_size)
{
    (void)in_sizes; (void)n_in; (void)out_size;
    const float* x = (const float*)d_in[0];
    float* out = (float*)d_out;
    dim3 grid(H, BATCH);
    LocalVariation_kernel<<<grid, 128>>>(x, out);
}

// round 2
// speedup vs baseline: 1.0572x; 1.0572x over previous
#include <cuda_runtime.h>
#include <cstddef>

// LocalVariation: out[b,k,y,x] = x[b,y,x] - x[b, clamp(y+i-2), clamp(x+j-2)]
// k enumerates 24 off-center (i,j) in a 5x5 window. x: [16,1,512,512] f32.
//
// R2: 4 output rows per CTA (512 threads). Stage 8 input rows once; each
// thread emits 4 contiguous pixels of one row for all 24 channels via
// streaming STG.128 (__stcs). Improves per-plane store contiguity (2KB->8KB
// per CTA), cuts staged L2 reads per output row 5->2, amortizes sync.

#define KSZ 5
#define P   2
#define NBR 24
#define H   512
#define W   512
#define BATCH 16
#define ROWS_PER_CTA 4
#define SROWS (ROWS_PER_CTA + KSZ - 1)   // 8 staged rows

// padded shared row: 516 valid cols (x in [-2,513]) -> stride 520 floats
// (multiple of 8 -> 16B-aligned rows)
#define SROW 520
#define SCOLS 516

__global__ __launch_bounds__(512, 2)
void LocalVariation_kernel(const float* __restrict__ x, float* __restrict__ out)
{
    __shared__ float s[SROWS * SROW];

    const int y0  = blockIdx.x * ROWS_PER_CTA;   // first output row of this CTA
    const int b   = blockIdx.y;                  // 0..15
    const int tid = threadIdx.x;                 // 0..511

    const float* __restrict__ xb = x + (size_t)b * H * W;

    // Stage rows y0-2 .. y0+5 (clamped) with x replicate-pad into SMEM.
    // 8*516 = 4128 scalar loads across 512 threads (~8 each); input is
    // L2-resident.
    #pragma unroll 2
    for (int idx = tid; idx < SROWS * SCOLS; idx += 512) {
        const int r   = idx / SCOLS;
        const int col = idx - r * SCOLS;         // 0..515  (maps to x = col-2)
        int gy = y0 + r - P;
        gy = gy < 0 ? 0 : (gy > H - 1 ? H - 1 : gy);
        int gx = col - P;
        gx = gx < 0 ? 0 : (gx > W - 1 ? W - 1 : gx);
        s[r * SROW + col] = __ldg(&xb[gy * W + gx]);
    }
    __syncthreads();

    const int r0 = tid >> 7;           // which of the 4 output rows (0..3)
    const int x0 = (tid & 127) * 4;    // this thread's 4 output pixels

    // 8-wide register window per needed row: smem rows r0..r0+4,
    // positions x0 .. x0+7. 16B-aligned -> LDS.128, conflict-free.
    float r[KSZ][8];
    #pragma unroll
    for (int i = 0; i < KSZ; i++) {
        const float* sp = &s[(r0 + i) * SROW + x0];
        const float4 lo = *reinterpret_cast<const float4*>(sp);
        const float4 hi = *reinterpret_cast<const float4*>(sp + 4);
        r[i][0] = lo.x; r[i][1] = lo.y; r[i][2] = lo.z; r[i][3] = lo.w;
        r[i][4] = hi.x; r[i][5] = hi.y; r[i][6] = hi.z; r[i][7] = hi.w;
    }

    // Center pixels: row y0+r0 = staged row r0+2, x offset +2.
    const float c0 = r[P][2];
    const float c1 = r[P][3];
    const float c2 = r[P][4];
    const float c3 = r[P][5];

    float* __restrict__ ob =
        out + (((size_t)b * NBR) * H + (y0 + r0)) * W + x0;

    int k = 0;
    #pragma unroll
    for (int i = 0; i < KSZ; i++) {
        #pragma unroll
        for (int j = 0; j < KSZ; j++) {
            if (i == P && j == P) continue;
            float4 v;
            v.x = c0 - r[i][j + 0];
            v.y = c1 - r[i][j + 1];
            v.z = c2 - r[i][j + 2];
            v.w = c3 - r[i][j + 3];
            // streaming store: evict-first in L2, don't thrash input residency
            __stcs(reinterpret_cast<float4*>(ob + (size_t)k * (H * W)), v);
            k++;
        }
    }
}

extern "C" void kernel_launch(void* const* d_in, const int* in_sizes, int n_in,
                              void* d_out, int out_size)
{
    (void)in_sizes; (void)n_in; (void)out_size;
    const float* x = (const float*)d_in[0];
    float* out = (float*)d_out;
    dim3 grid(H / ROWS_PER_CTA, BATCH);
    LocalVariation_kernel<<<grid, 512>>>(x, out);
}

// round 3
// speedup vs baseline: 1.1096x; 1.0495x over previous
#include <cuda_runtime.h>
#include <cstddef>

// LocalVariation: out[b,k,y,x] = x[b,y,x] - x[b, clamp(y+i-2), clamp(x+j-2)]
// k enumerates 24 off-center (i,j) in a 5x5 window. x: [16,1,512,512] f32.
//
// R3: reduce register pressure (per-row window instead of hoisted 5x8 array)
// + __launch_bounds__(512,3) -> 48 warps/SM for more store-level parallelism.
// Store stream stays __stcs STG.128.

#define KSZ 5
#define P   2
#define NBR 24
#define H   512
#define W   512
#define BATCH 16
#define ROWS_PER_CTA 4
#define SROWS (ROWS_PER_CTA + KSZ - 1)   // 8 staged rows

// padded shared row: 516 valid cols (x in [-2,513]) -> stride 520 floats
#define SROW 520
#define SCOLS 516

__global__ __launch_bounds__(512, 3)
void LocalVariation_kernel(const float* __restrict__ x, float* __restrict__ out)
{
    __shared__ float s[SROWS * SROW];

    const int y0  = blockIdx.x * ROWS_PER_CTA;   // first output row of this CTA
    const int b   = blockIdx.y;                  // 0..15
    const int tid = threadIdx.x;                 // 0..511

    const float* __restrict__ xb = x + (size_t)b * H * W;

    // Stage rows y0-2 .. y0+5 (clamped) with x replicate-pad into SMEM.
    #pragma unroll 2
    for (int idx = tid; idx < SROWS * SCOLS; idx += 512) {
        const int r   = idx / SCOLS;
        const int col = idx - r * SCOLS;         // 0..515  (maps to x = col-2)
        int gy = y0 + r - P;
        gy = gy < 0 ? 0 : (gy > H - 1 ? H - 1 : gy);
        int gx = col - P;
        gx = gx < 0 ? 0 : (gx > W - 1 ? W - 1 : gx);
        s[r * SROW + col] = __ldg(&xb[gy * W + gx]);
    }
    __syncthreads();

    const int r0 = tid >> 7;           // which of the 4 output rows (0..3)
    const int x0 = (tid & 127) * 4;    // this thread's 4 output pixels

    // Center pixels: staged row r0+2, x offset +2..+5.
    const float c0 = s[(r0 + P) * SROW + x0 + 2];
    const float c1 = s[(r0 + P) * SROW + x0 + 3];
    const float c2 = s[(r0 + P) * SROW + x0 + 4];
    const float c3 = s[(r0 + P) * SROW + x0 + 5];

    float* __restrict__ ob =
        out + (((size_t)b * NBR) * H + (y0 + r0)) * W + x0;

    // Per input row: load an 8-wide window (two aligned LDS.128), emit that
    // row's 4-5 channel stores, then release the window regs. Keeps the live
    // set ~20 regs so 3 CTAs/SM fit.
    int k = 0;
    #pragma unroll
    for (int i = 0; i < KSZ; i++) {
        const float* sp = &s[(r0 + i) * SROW + x0];
        const float4 lo = *reinterpret_cast<const float4*>(sp);
        const float4 hi = *reinterpret_cast<const float4*>(sp + 4);
        float w[8];
        w[0] = lo.x; w[1] = lo.y; w[2] = lo.z; w[3] = lo.w;
        w[4] = hi.x; w[5] = hi.y; w[6] = hi.z; w[7] = hi.w;

        #pragma unroll
        for (int j = 0; j < KSZ; j++) {
            if (i == P && j == P) continue;
            float4 v;
            v.x = c0 - w[j + 0];
            v.y = c1 - w[j + 1];
            v.z = c2 - w[j + 2];
            v.w = c3 - w[j + 3];
            __stcs(reinterpret_cast<float4*>(ob + (size_t)k * (H * W)), v);
            k++;
        }
    }
}

extern "C" void kernel_launch(void* const* d_in, const int* in_sizes, int n_in,
                              void* d_out, int out_size)
{
    (void)in_sizes; (void)n_in; (void)out_size;
    const float* x = (const float*)d_in[0];
    float* out = (float*)d_out;
    dim3 grid(H / ROWS_PER_CTA, BATCH);
    LocalVariation_kernel<<<grid, 512>>>(x, out);
}